// round 13
// baseline (speedup 1.0000x reference)
#include <cuda_runtime.h>
#include <cuda_bf16.h>
#include <cstdint>

#define HW   4096
#define NB   4
#define CIN  256
#define DQK  64
#define BQ   32           // queries per CTA
#define BK   32           // keys per iteration
#define NITER (HW / BK)   // 128

// (1/16) * log2(e), folded into Q at projection time
#define QSCL (0.0625f * 1.44269504088896f)
#define ONESB2 0x3F803F80u   /* bf16x2 {1.0, 1.0} */

// ---------------- scratch (bf16) ----------------
__device__ __nv_bfloat16 Qg[NB * HW * DQK];        // [b][i][k]   2 MB (pre-scaled)
__device__ __nv_bfloat16 Kg[NB * HW * DQK];        // [b][j][k]   2 MB
__device__ __nv_bfloat16 Vtg[NB * CIN * HW];       // [b][c][j]   8 MB (channel-major)

// ---------------- helpers ----------------
__device__ __forceinline__ uint32_t smem_u32(const void* p) {
    uint32_t a;
    asm("{ .reg .u64 t; cvta.to.shared.u64 t, %1; cvt.u32.u64 %0, t; }" : "=r"(a) : "l"(p));
    return a;
}
__device__ __forceinline__ void cp_async16(uint32_t dst, const void* src) {
    asm volatile("cp.async.cg.shared.global [%0], [%1], 16;" :: "r"(dst), "l"(src));
}
#define CP_COMMIT() asm volatile("cp.async.commit_group;" ::: "memory")

__device__ __forceinline__ uint32_t lds_b32(uint32_t a) {
    uint32_t v;
    asm volatile("ld.shared.b32 %0, [%1];" : "=r"(v) : "r"(a));
    return v;
}
__device__ __forceinline__ void sts_b32(uint32_t a, uint32_t v) {
    asm volatile("st.shared.b32 [%0], %1;" :: "r"(a), "r"(v) : "memory");
}
__device__ __forceinline__ void ldmx4(uint32_t* r, uint32_t a) {
    asm volatile("ldmatrix.sync.aligned.m8n8.x4.shared.b16 {%0,%1,%2,%3}, [%4];"
                 : "=r"(r[0]), "=r"(r[1]), "=r"(r[2]), "=r"(r[3]) : "r"(a));
}
__device__ __forceinline__ uint32_t cvt_bf16x2(float lo, float hi) {
    uint32_t r;
    asm("cvt.rn.bf16x2.f32 %0, %1, %2;" : "=r"(r) : "f"(hi), "f"(lo));
    return r;
}
__device__ __forceinline__ uint32_t ex2_b2(uint32_t x) {
    uint32_t r;
    asm("ex2.approx.ftz.bf16x2 %0, %1;" : "=r"(r) : "r"(x));
    return r;
}
// D += A(16x16,row) * B(16x8,col)  bf16 -> f32
__device__ __forceinline__ void mma16816(float* c,
                                         uint32_t a0, uint32_t a1, uint32_t a2, uint32_t a3,
                                         uint32_t b0, uint32_t b1) {
    asm volatile(
        "mma.sync.aligned.m16n8k16.row.col.f32.bf16.bf16.f32 "
        "{%0,%1,%2,%3}, {%4,%5,%6,%7}, {%8,%9}, {%0,%1,%2,%3};"
        : "+f"(c[0]), "+f"(c[1]), "+f"(c[2]), "+f"(c[3])
        : "r"(a0), "r"(a1), "r"(a2), "r"(a3), "r"(b0), "r"(b1));
}
// D += A(16x8,row) * B(8x8,col)  tf32 -> f32
__device__ __forceinline__ void mma_tf32(float* c,
                                         uint32_t a0, uint32_t a1, uint32_t a2, uint32_t a3,
                                         uint32_t b0, uint32_t b1) {
    asm volatile(
        "mma.sync.aligned.m16n8k8.row.col.f32.tf32.tf32.f32 "
        "{%0,%1,%2,%3}, {%4,%5,%6,%7}, {%8,%9}, {%0,%1,%2,%3};"
        : "+f"(c[0]), "+f"(c[1]), "+f"(c[2]), "+f"(c[3])
        : "r"(a0), "r"(a1), "r"(a2), "r"(a3), "r"(b0), "r"(b1));
}

// ---------------- attn SMEM layout (bytes) ----------------
#define KROW 144                   // 64 bf16 + pad
#define VROW 80                    // 32 bf16 + pad
#define PROW 80                    // 32 bf16 + pad
#define SM_Q   0                   // 32 x 144 =  4608
#define SM_K0  4608                // 32 x 144 =  4608
#define SM_K1  9216
#define SM_V0  13824               // 256 x 80 = 20480
#define SM_V1  34304
#define SM_P   54784               // 32 x 80  =  2560
#define SM_DEN 57344               // 64 floats = 256
#define SM_TOTAL 57600
#define STGROW 36                  // epilogue staging [256 ch][36] floats @ offset 0

// ---------------- proj SMEM layout (bytes) ----------------
#define XROWB 544
#define WROWB 272
#define PX0 0
#define PX1 34816
#define PW0 69632
#define PW1 87040
#define P_TOTAL 104448
#define PSTGROW 144

// ============================================================
// Projection via tf32 tensor cores. (unchanged from round 10)
// ============================================================
__global__ __launch_bounds__(128, 2) void proj_tc(
    const float* __restrict__ src, const float* __restrict__ ref,
    const float* __restrict__ w_src, const float* __restrict__ b_src,
    const float* __restrict__ w_ref, const float* __restrict__ b_ref,
    const float* __restrict__ w_gate, const float* __restrict__ b_gate)
{
    extern __shared__ char smem[];
    const uint32_t sb = smem_u32(smem);
    const int tid  = threadIdx.x;
    const int warp = tid >> 5;
    const int lane = tid & 31;
    const int row4 = lane >> 2;
    const int q4   = lane & 3;
    const int z    = blockIdx.z;
    const int b    = blockIdx.y;
    const int i0   = blockIdx.x * 128;

    const float *X, *W, *bias;
    if (z == 0)      { X = src; W = w_src;                       bias = b_src; }
    else if (z == 1) { X = ref; W = w_ref;                       bias = b_ref; }
    else             { X = ref; W = w_gate + (z - 2) * 64 * CIN; bias = b_gate + (z - 2) * 64; }
    const float* Xb = X + (size_t)b * CIN * HW;

    auto issue_chunk = [&](int kc, int buf) {
        const uint32_t xb = sb + (buf ? PX1 : PX0);
        const uint32_t wb = sb + (buf ? PW1 : PW0);
        #pragma unroll
        for (int t = tid; t < 64 * 32; t += 128) {
            int r = t >> 5, s = t & 31;
            cp_async16(xb + r * XROWB + s * 16, Xb + (size_t)(kc * 64 + r) * HW + i0 + s * 4);
        }
        #pragma unroll
        for (int t = tid; t < 64 * 16; t += 128) {
            int r = t >> 4, s = t & 15;
            cp_async16(wb + r * WROWB + s * 16, W + r * CIN + kc * 64 + s * 4);
        }
    };

    issue_chunk(0, 0);
    CP_COMMIT();

    float acc[16][4];
    #pragma unroll
    for (int nt = 0; nt < 16; nt++)
        #pragma unroll
        for (int c = 0; c < 4; c++) acc[nt][c] = 0.f;

    #pragma unroll 1
    for (int kc = 0; kc < 4; kc++) {
        if (kc + 1 < 4) {
            issue_chunk(kc + 1, (kc + 1) & 1);
            CP_COMMIT();
            asm volatile("cp.async.wait_group 1;" ::: "memory");
        } else {
            asm volatile("cp.async.wait_group 0;" ::: "memory");
        }
        __syncthreads();

        const uint32_t xb = sb + ((kc & 1) ? PX1 : PX0);
        const uint32_t wb = sb + ((kc & 1) ? PW1 : PW0);
        const uint32_t abase = wb + (warp * 16 + row4) * WROWB + q4 * 4;
        const uint32_t bbase = xb + q4 * XROWB + row4 * 4;

        #pragma unroll
        for (int ks = 0; ks < 8; ks++) {
            uint32_t a0 = lds_b32(abase + ks * 32);
            uint32_t a1 = lds_b32(abase + 8 * WROWB + ks * 32);
            uint32_t a2 = lds_b32(abase + ks * 32 + 16);
            uint32_t a3 = lds_b32(abase + 8 * WROWB + ks * 32 + 16);
            const uint32_t bk = bbase + ks * 8 * XROWB;
            #pragma unroll
            for (int nt = 0; nt < 16; nt++) {
                uint32_t b0 = lds_b32(bk + nt * 32);
                uint32_t b1 = lds_b32(bk + 4 * XROWB + nt * 32);
                mma_tf32(acc[nt], a0, a1, a2, a3, b0, b1);
            }
        }
        __syncthreads();
    }

    const int olo = warp * 16 + row4;
    const float bv0 = bias[olo];
    const float bv8 = bias[olo + 8];

    if (z >= 2) {
        const int ch0 = (z - 2) * 64;
        #pragma unroll
        for (int nt = 0; nt < 16; nt++) {
            const int i = i0 + nt * 8 + 2 * q4;
            *(uint32_t*)(Vtg + ((size_t)(b * CIN + ch0 + olo)) * HW + i) =
                cvt_bf16x2(acc[nt][0] + bv0, acc[nt][1] + bv0);
            *(uint32_t*)(Vtg + ((size_t)(b * CIN + ch0 + olo + 8)) * HW + i) =
                cvt_bf16x2(acc[nt][2] + bv8, acc[nt][3] + bv8);
        }
    } else {
        const float s = (z == 0) ? QSCL : 1.0f;
        __nv_bfloat16* stg = (__nv_bfloat16*)smem;
        #pragma unroll
        for (int nt = 0; nt < 16; nt++) {
            const int i = nt * 8 + 2 * q4;
            __nv_bfloat16* r0 = stg + (size_t)i * (PSTGROW / 2);
            r0[olo]     = __float2bfloat16((acc[nt][0] + bv0) * s);
            r0[olo + 8] = __float2bfloat16((acc[nt][2] + bv8) * s);
            __nv_bfloat16* r1 = stg + (size_t)(i + 1) * (PSTGROW / 2);
            r1[olo]     = __float2bfloat16((acc[nt][1] + bv0) * s);
            r1[olo + 8] = __float2bfloat16((acc[nt][3] + bv8) * s);
        }
        __syncthreads();
        __nv_bfloat16* outp = (z == 0 ? Qg : Kg) + ((size_t)b * HW + i0) * DQK;
        #pragma unroll
        for (int t = tid; t < 1024; t += 128) {
            int r = t >> 3, seg = t & 7;
            *(uint4*)(outp + (size_t)r * DQK + seg * 8) =
                *(uint4*)((char*)smem + r * PSTGROW + seg * 16);
        }
    }
}

// ============================================================
// Flash attention, P shared via SMEM (S computed once per CTA).
// grid (HW/32=128, NB). 128 threads.
// S phase:  warp w -> m-tile (w>>1), key-half (w&1)   : 16q x 16k
// PV phase: warp w -> m-tile (w>>1), chan-half (w&1)  : 16q x 128ch
// ============================================================
__device__ __forceinline__ void issue_kv(uint32_t sb, int koff, int voff,
                                         int b, int j0, int tid)
{
    const __nv_bfloat16* kp = Kg + ((size_t)b * HW + j0) * DQK;
    #pragma unroll
    for (int t = tid; t < 32 * 8; t += 128) {
        int r = t >> 3, c8 = t & 7;
        cp_async16(sb + koff + r * KROW + c8 * 16, kp + r * DQK + c8 * 8);
    }
    #pragma unroll
    for (int t = tid; t < 256 * 4; t += 128) {
        int c = t >> 2, s = t & 3;
        cp_async16(sb + voff + c * VROW + s * 16,
                   Vtg + ((size_t)(b * CIN + c)) * HW + j0 + s * 8);
    }
}

__global__ __launch_bounds__(128, 3) void attn_kernel(
    const float* __restrict__ srcf, const float* __restrict__ gammap,
    float* __restrict__ out)
{
    extern __shared__ char smem[];
    const uint32_t sb = smem_u32(smem);
    const int tid  = threadIdx.x;
    const int warp = tid >> 5;
    const int lane = tid & 31;
    const int b    = blockIdx.y;
    const int q0   = blockIdx.x * BQ;
    const int qr   = (lane >> 2);        // 0..7
    const int m4   = (lane & 3);         // 0..3
    const int mt   = warp >> 1;          // m-tile 0/1
    const int half = warp & 1;           // key-half (S) / chan-half (PV)

    // ldmatrix B-frag lane offsets
    const uint32_t lmoffK = (uint32_t)((((lane >> 4) & 1) * 8 + (lane & 7)) * KROW
                                       + ((lane >> 3) & 1) * 16);
    const uint32_t lmoffV = (uint32_t)((((lane >> 4) & 1) * 8 + (lane & 7)) * VROW
                                       + ((lane >> 3) & 1) * 16);
    // ldmatrix A-frag addr for P (this warp's m-tile, 16 rows x 32 keys)
    const uint32_t pA = sb + SM_P + (mt * 16 + (lane & 15)) * PROW + ((lane >> 4) & 1) * 16;

    // prologue: Q (group 0), K0/V0 (group 1)
    {
        const __nv_bfloat16* qp = Qg + ((size_t)b * HW + q0) * DQK;
        #pragma unroll
        for (int t = tid; t < 32 * 8; t += 128) {
            int r = t >> 3, c8 = t & 7;
            cp_async16(sb + SM_Q + r * KROW + c8 * 16, qp + r * DQK + c8 * 8);
        }
        CP_COMMIT();
        issue_kv(sb, SM_K0, SM_V0, b, 0, tid);
        CP_COMMIT();
    }

    // Q A-frags for this warp's m-tile
    uint32_t aq[4][4];
    {
        asm volatile("cp.async.wait_group 1;" ::: "memory");
        __syncthreads();
        const uint32_t qbase = sb + SM_Q + (mt * 16 + qr) * KROW + m4 * 4;
        #pragma unroll
        for (int ks = 0; ks < 4; ks++) {
            aq[ks][0] = lds_b32(qbase + ks * 32);
            aq[ks][1] = lds_b32(qbase + 8 * KROW + ks * 32);
            aq[ks][2] = lds_b32(qbase + ks * 32 + 16);
            aq[ks][3] = lds_b32(qbase + 8 * KROW + ks * 32 + 16);
        }
    }

    float oacc[16][4];
    #pragma unroll
    for (int nt = 0; nt < 16; nt++)
        #pragma unroll
        for (int c = 0; c < 4; c++) oacc[nt][c] = 0.f;
    float dden[4];
    #pragma unroll
    for (int c = 0; c < 4; c++) dden[c] = 0.f;

    const uint32_t pstore = sb + SM_P + (mt * 16 + qr) * PROW + half * 32 + m4 * 4;

    #pragma unroll 1
    for (int j = 0; j < NITER; j++) {
        const int koff = (j & 1) ? SM_K1 : SM_K0;
        const int voff = (j & 1) ? SM_V1 : SM_V0;

        asm volatile("cp.async.wait_group 0;" ::: "memory");
        __syncthreads();   // K/V(j) visible; prev PV done (P/other-buf writable)

        // ---- S phase: 16q x 16k for (mt, key-half) ----
        {
            const uint32_t kbase = sb + koff + half * 16 * KROW + lmoffK;
            float s2[2][4];
            #pragma unroll
            for (int nh = 0; nh < 2; nh++)
                #pragma unroll
                for (int c = 0; c < 4; c++) s2[nh][c] = 0.f;
            #pragma unroll
            for (int ks = 0; ks < 4; ks++) {
                uint32_t kf[4];
                ldmx4(kf, kbase + ks * 32);
                mma16816(s2[0], aq[ks][0], aq[ks][1], aq[ks][2], aq[ks][3], kf[0], kf[1]);
                mma16816(s2[1], aq[ks][0], aq[ks][1], aq[ks][2], aq[ks][3], kf[2], kf[3]);
            }
            uint32_t pa0 = ex2_b2(cvt_bf16x2(s2[0][0], s2[0][1]));
            uint32_t pa1 = ex2_b2(cvt_bf16x2(s2[0][2], s2[0][3]));
            uint32_t pa2 = ex2_b2(cvt_bf16x2(s2[1][0], s2[1][1]));
            uint32_t pa3 = ex2_b2(cvt_bf16x2(s2[1][2], s2[1][3]));
            sts_b32(pstore,              pa0);
            sts_b32(pstore + 8 * PROW,   pa1);
            sts_b32(pstore + 16,         pa2);
            sts_b32(pstore + 8 * PROW + 16, pa3);
            mma16816(dden, pa0, pa1, pa2, pa3, ONESB2, ONESB2);
        }

        // prefetch K/V(j+1) into the other buffer (safe: sync above)
        if (j + 1 < NITER)
            issue_kv(sb, (j & 1) ? SM_K0 : SM_K1, (j & 1) ? SM_V0 : SM_V1,
                     b, (j + 1) * BK, tid);
        CP_COMMIT();

        __syncthreads();   // P visible to all warps

        // ---- PV phase: 16q x 128ch for (mt, chan-half) ----
        {
            uint32_t pf[2][4];
            ldmx4(pf[0], pA);          // keys 0-15
            ldmx4(pf[1], pA + 32);     // keys 16-31
            const uint32_t vbase = sb + voff + half * 128 * VROW + lmoffV;
            #pragma unroll
            for (int ks2 = 0; ks2 < 2; ks2++) {
                #pragma unroll
                for (int ntp = 0; ntp < 8; ntp++) {
                    uint32_t vf[4];
                    ldmx4(vf, vbase + ntp * (16 * VROW) + ks2 * 32);
                    mma16816(oacc[2 * ntp],     pf[ks2][0], pf[ks2][1],
                             pf[ks2][2], pf[ks2][3], vf[0], vf[1]);
                    mma16816(oacc[2 * ntp + 1], pf[ks2][0], pf[ks2][1],
                             pf[ks2][2], pf[ks2][3], vf[2], vf[3]);
                }
            }
        }
    }

    // ---- den: combine key-halves across warps ----
    float* den_sm = (float*)(smem + SM_DEN);   // [2 halves][32 rows]
    const int row = mt * 16 + qr;
    den_sm[half * 32 + row]     = dden[0];
    den_sm[half * 32 + row + 8] = dden[2];
    __syncthreads();
    const float gamma = __ldg(gammap);
    const float scl0 = gamma / (den_sm[row]     + den_sm[32 + row]);
    const float scl8 = gamma / (den_sm[row + 8] + den_sm[32 + row + 8]);
    __syncthreads();

    // ---- epilogue: stage [256 ch][36] fp32 at smem offset 0, coalesced out ----
    float* stg = (float*)smem;
    #pragma unroll
    for (int nt = 0; nt < 16; nt++) {
        const int ch = half * 128 + nt * 8 + 2 * m4;
        stg[ch * STGROW + row]           = oacc[nt][0] * scl0;
        stg[(ch + 1) * STGROW + row]     = oacc[nt][1] * scl0;
        stg[ch * STGROW + row + 8]       = oacc[nt][2] * scl8;
        stg[(ch + 1) * STGROW + row + 8] = oacc[nt][3] * scl8;
    }
    __syncthreads();
    const float* sp = srcf + (size_t)b * CIN * HW;
    float*       op = out  + (size_t)b * CIN * HW;
    #pragma unroll
    for (int idx = tid; idx < 256 * 8; idx += 128) {
        const int ch = idx >> 3, qq = (idx & 7) * 4;
        float4 v = *(const float4*)&stg[ch * STGROW + qq];
        const size_t g = (size_t)ch * HW + q0 + qq;
        float4 s4 = *(const float4*)&sp[g];
        v.x += s4.x; v.y += s4.y; v.z += s4.z; v.w += s4.w;
        *(float4*)&op[g] = v;
    }
}

// ============================================================
extern "C" void kernel_launch(void* const* d_in, const int* in_sizes, int n_in,
                              void* d_out, int out_size)
{
    const float* src    = (const float*)d_in[0];
    const float* ref    = (const float*)d_in[1];
    const float* w_src  = (const float*)d_in[2];
    const float* b_src  = (const float*)d_in[3];
    const float* w_ref  = (const float*)d_in[4];
    const float* b_ref  = (const float*)d_in[5];
    const float* w_gate = (const float*)d_in[6];
    const float* b_gate = (const float*)d_in[7];
    const float* gamma  = (const float*)d_in[8];
    float* out = (float*)d_out;

    cudaFuncSetAttribute(proj_tc, cudaFuncAttributeMaxDynamicSharedMemorySize, P_TOTAL);
    cudaFuncSetAttribute(attn_kernel, cudaFuncAttributeMaxDynamicSharedMemorySize, SM_TOTAL);

    proj_tc<<<dim3(HW / 128, NB, 6), 128, P_TOTAL>>>(src, ref, w_src, b_src,
                                                     w_ref, b_ref, w_gate, b_gate);
    attn_kernel<<<dim3(HW / BQ, NB), 128, SM_TOTAL>>>(src, gamma, out);
}

// round 14
// speedup vs baseline: 1.3500x; 1.3500x over previous
#include <cuda_runtime.h>
#include <cuda_bf16.h>
#include <cstdint>

#define HW   4096
#define NB   4
#define CIN  256
#define DQK  64
#define BQ   32           // queries per CTA
#define BK   64           // keys per iteration
#define NITER (HW / BK)   // 64

// (1/16) * log2(e), folded into Q at projection time
#define QSCL (0.0625f * 1.44269504088896f)
#define ONESB2 0x3F803F80u   /* bf16x2 {1.0, 1.0} */

// ---------------- scratch (bf16) ----------------
__device__ __nv_bfloat16 Qg[NB * HW * DQK];        // [b][i][k]   2 MB (pre-scaled)
__device__ __nv_bfloat16 Kg[NB * HW * DQK];        // [b][j][k]   2 MB
__device__ __nv_bfloat16 Vtg[NB * CIN * HW];       // [b][c][j]   8 MB (channel-major)

// ---------------- helpers ----------------
__device__ __forceinline__ uint32_t smem_u32(const void* p) {
    uint32_t a;
    asm("{ .reg .u64 t; cvta.to.shared.u64 t, %1; cvt.u32.u64 %0, t; }" : "=r"(a) : "l"(p));
    return a;
}
__device__ __forceinline__ void cp_async16(uint32_t dst, const void* src) {
    asm volatile("cp.async.cg.shared.global [%0], [%1], 16;" :: "r"(dst), "l"(src));
}
#define CP_COMMIT() asm volatile("cp.async.commit_group;" ::: "memory")

__device__ __forceinline__ uint32_t lds_b32(uint32_t a) {
    uint32_t v;
    asm volatile("ld.shared.b32 %0, [%1];" : "=r"(v) : "r"(a));
    return v;
}
__device__ __forceinline__ void sts_b32(uint32_t a, uint32_t v) {
    asm volatile("st.shared.b32 [%0], %1;" :: "r"(a), "r"(v) : "memory");
}
__device__ __forceinline__ void ldmx4(uint32_t* r, uint32_t a) {
    asm volatile("ldmatrix.sync.aligned.m8n8.x4.shared.b16 {%0,%1,%2,%3}, [%4];"
                 : "=r"(r[0]), "=r"(r[1]), "=r"(r[2]), "=r"(r[3]) : "r"(a));
}
__device__ __forceinline__ uint32_t cvt_bf16x2(float lo, float hi) {
    uint32_t r;
    asm("cvt.rn.bf16x2.f32 %0, %1, %2;" : "=r"(r) : "f"(hi), "f"(lo));
    return r;
}
__device__ __forceinline__ uint32_t ex2_b2(uint32_t x) {
    uint32_t r;
    asm("ex2.approx.ftz.bf16x2 %0, %1;" : "=r"(r) : "r"(x));
    return r;
}
// D += A(16x16,row) * B(16x8,col)  bf16 -> f32
__device__ __forceinline__ void mma16816(float* c,
                                         uint32_t a0, uint32_t a1, uint32_t a2, uint32_t a3,
                                         uint32_t b0, uint32_t b1) {
    asm volatile(
        "mma.sync.aligned.m16n8k16.row.col.f32.bf16.bf16.f32 "
        "{%0,%1,%2,%3}, {%4,%5,%6,%7}, {%8,%9}, {%0,%1,%2,%3};"
        : "+f"(c[0]), "+f"(c[1]), "+f"(c[2]), "+f"(c[3])
        : "r"(a0), "r"(a1), "r"(a2), "r"(a3), "r"(b0), "r"(b1));
}
// D += A(16x8,row) * B(8x8,col)  tf32 -> f32
__device__ __forceinline__ void mma_tf32(float* c,
                                         uint32_t a0, uint32_t a1, uint32_t a2, uint32_t a3,
                                         uint32_t b0, uint32_t b1) {
    asm volatile(
        "mma.sync.aligned.m16n8k8.row.col.f32.tf32.tf32.f32 "
        "{%0,%1,%2,%3}, {%4,%5,%6,%7}, {%8,%9}, {%0,%1,%2,%3};"
        : "+f"(c[0]), "+f"(c[1]), "+f"(c[2]), "+f"(c[3])
        : "r"(a0), "r"(a1), "r"(a2), "r"(a3), "r"(b0), "r"(b1));
}

// ---------------- attn SMEM layout (bytes) ----------------
#define KROW 144                   // 64 bf16 (dqk) + pad
#define VROW 144                   // 64 bf16 (keys) + pad
#define PROW 144                   // 64 bf16 (keys) + pad
#define SM_Q   0                   // 32 x 144  =  4608
#define SM_K0  4608                // 64 x 144  =  9216
#define SM_K1  13824
#define SM_V0  23040               // 256 x 144 = 36864
#define SM_V1  59904
#define SM_P   96768               // 32 x 144  =  4608
#define SM_DEN 101376              // 64 floats = 256
#define SM_TOTAL 101632
#define STGROW 36                  // epilogue staging [256 ch][36] floats @ offset 0

// ---------------- proj SMEM layout (bytes) ----------------
#define XROWB 544
#define WROWB 272
#define PX0 0
#define PX1 34816
#define PW0 69632
#define PW1 87040
#define P_TOTAL 104448
#define PSTGROW 144

// ============================================================
// Projection via tf32 tensor cores. (unchanged from round 10)
// ============================================================
__global__ __launch_bounds__(128, 2) void proj_tc(
    const float* __restrict__ src, const float* __restrict__ ref,
    const float* __restrict__ w_src, const float* __restrict__ b_src,
    const float* __restrict__ w_ref, const float* __restrict__ b_ref,
    const float* __restrict__ w_gate, const float* __restrict__ b_gate)
{
    extern __shared__ char smem[];
    const uint32_t sb = smem_u32(smem);
    const int tid  = threadIdx.x;
    const int warp = tid >> 5;
    const int lane = tid & 31;
    const int row4 = lane >> 2;
    const int q4   = lane & 3;
    const int z    = blockIdx.z;
    const int b    = blockIdx.y;
    const int i0   = blockIdx.x * 128;

    const float *X, *W, *bias;
    if (z == 0)      { X = src; W = w_src;                       bias = b_src; }
    else if (z == 1) { X = ref; W = w_ref;                       bias = b_ref; }
    else             { X = ref; W = w_gate + (z - 2) * 64 * CIN; bias = b_gate + (z - 2) * 64; }
    const float* Xb = X + (size_t)b * CIN * HW;

    auto issue_chunk = [&](int kc, int buf) {
        const uint32_t xb = sb + (buf ? PX1 : PX0);
        const uint32_t wb = sb + (buf ? PW1 : PW0);
        #pragma unroll
        for (int t = tid; t < 64 * 32; t += 128) {
            int r = t >> 5, s = t & 31;
            cp_async16(xb + r * XROWB + s * 16, Xb + (size_t)(kc * 64 + r) * HW + i0 + s * 4);
        }
        #pragma unroll
        for (int t = tid; t < 64 * 16; t += 128) {
            int r = t >> 4, s = t & 15;
            cp_async16(wb + r * WROWB + s * 16, W + r * CIN + kc * 64 + s * 4);
        }
    };

    issue_chunk(0, 0);
    CP_COMMIT();

    float acc[16][4];
    #pragma unroll
    for (int nt = 0; nt < 16; nt++)
        #pragma unroll
        for (int c = 0; c < 4; c++) acc[nt][c] = 0.f;

    #pragma unroll 1
    for (int kc = 0; kc < 4; kc++) {
        if (kc + 1 < 4) {
            issue_chunk(kc + 1, (kc + 1) & 1);
            CP_COMMIT();
            asm volatile("cp.async.wait_group 1;" ::: "memory");
        } else {
            asm volatile("cp.async.wait_group 0;" ::: "memory");
        }
        __syncthreads();

        const uint32_t xb = sb + ((kc & 1) ? PX1 : PX0);
        const uint32_t wb = sb + ((kc & 1) ? PW1 : PW0);
        const uint32_t abase = wb + (warp * 16 + row4) * WROWB + q4 * 4;
        const uint32_t bbase = xb + q4 * XROWB + row4 * 4;

        #pragma unroll
        for (int ks = 0; ks < 8; ks++) {
            uint32_t a0 = lds_b32(abase + ks * 32);
            uint32_t a1 = lds_b32(abase + 8 * WROWB + ks * 32);
            uint32_t a2 = lds_b32(abase + ks * 32 + 16);
            uint32_t a3 = lds_b32(abase + 8 * WROWB + ks * 32 + 16);
            const uint32_t bk = bbase + ks * 8 * XROWB;
            #pragma unroll
            for (int nt = 0; nt < 16; nt++) {
                uint32_t b0 = lds_b32(bk + nt * 32);
                uint32_t b1 = lds_b32(bk + 4 * XROWB + nt * 32);
                mma_tf32(acc[nt], a0, a1, a2, a3, b0, b1);
            }
        }
        __syncthreads();
    }

    const int olo = warp * 16 + row4;
    const float bv0 = bias[olo];
    const float bv8 = bias[olo + 8];

    if (z >= 2) {
        const int ch0 = (z - 2) * 64;
        #pragma unroll
        for (int nt = 0; nt < 16; nt++) {
            const int i = i0 + nt * 8 + 2 * q4;
            *(uint32_t*)(Vtg + ((size_t)(b * CIN + ch0 + olo)) * HW + i) =
                cvt_bf16x2(acc[nt][0] + bv0, acc[nt][1] + bv0);
            *(uint32_t*)(Vtg + ((size_t)(b * CIN + ch0 + olo + 8)) * HW + i) =
                cvt_bf16x2(acc[nt][2] + bv8, acc[nt][3] + bv8);
        }
    } else {
        const float s = (z == 0) ? QSCL : 1.0f;
        __nv_bfloat16* stg = (__nv_bfloat16*)smem;
        #pragma unroll
        for (int nt = 0; nt < 16; nt++) {
            const int i = nt * 8 + 2 * q4;
            __nv_bfloat16* r0 = stg + (size_t)i * (PSTGROW / 2);
            r0[olo]     = __float2bfloat16((acc[nt][0] + bv0) * s);
            r0[olo + 8] = __float2bfloat16((acc[nt][2] + bv8) * s);
            __nv_bfloat16* r1 = stg + (size_t)(i + 1) * (PSTGROW / 2);
            r1[olo]     = __float2bfloat16((acc[nt][1] + bv0) * s);
            r1[olo + 8] = __float2bfloat16((acc[nt][3] + bv8) * s);
        }
        __syncthreads();
        __nv_bfloat16* outp = (z == 0 ? Qg : Kg) + ((size_t)b * HW + i0) * DQK;
        #pragma unroll
        for (int t = tid; t < 1024; t += 128) {
            int r = t >> 3, seg = t & 7;
            *(uint4*)(outp + (size_t)r * DQK + seg * 8) =
                *(uint4*)((char*)smem + r * PSTGROW + seg * 16);
        }
    }
}

// ============================================================
// Flash attention, P shared via SMEM, BK=64.
// grid (HW/32=128, NB). 128 threads, occ 2.
// S phase:  warp w -> m-tile (w>>1), key-half (w&1)   : 16q x 32k
// PV phase: warp w -> m-tile (w>>1), chan-half (w&1)  : 16q x 128ch x 64k
// ============================================================
__device__ __forceinline__ void issue_kv(uint32_t sb, int koff, int voff,
                                         int b, int j0, int tid)
{
    // K tile: 64 key-rows x 128B
    const __nv_bfloat16* kp = Kg + ((size_t)b * HW + j0) * DQK;
    #pragma unroll
    for (int t = tid; t < 64 * 8; t += 128) {
        int r = t >> 3, c8 = t & 7;
        cp_async16(sb + koff + r * KROW + c8 * 16, kp + r * DQK + c8 * 8);
    }
    // V tile: 256 channel-rows x 128B (64 keys)
    #pragma unroll
    for (int t = tid; t < 256 * 8; t += 128) {
        int c = t >> 3, s = t & 7;
        cp_async16(sb + voff + c * VROW + s * 16,
                   Vtg + ((size_t)(b * CIN + c)) * HW + j0 + s * 8);
    }
}

__global__ __launch_bounds__(128, 2) void attn_kernel(
    const float* __restrict__ srcf, const float* __restrict__ gammap,
    float* __restrict__ out)
{
    extern __shared__ char smem[];
    const uint32_t sb = smem_u32(smem);
    const int tid  = threadIdx.x;
    const int warp = tid >> 5;
    const int lane = tid & 31;
    const int b    = blockIdx.y;
    const int q0   = blockIdx.x * BQ;
    const int qr   = (lane >> 2);        // 0..7
    const int m4   = (lane & 3);         // 0..3
    const int mt   = warp >> 1;          // m-tile 0/1
    const int half = warp & 1;           // key-half (S) / chan-half (PV)

    // ldmatrix B-frag lane offsets (row pad 144B for both K and V)
    const uint32_t lmoffK = (uint32_t)((((lane >> 4) & 1) * 8 + (lane & 7)) * KROW
                                       + ((lane >> 3) & 1) * 16);
    const uint32_t lmoffV = (uint32_t)((((lane >> 4) & 1) * 8 + (lane & 7)) * VROW
                                       + ((lane >> 3) & 1) * 16);
    // ldmatrix A-frag base for P (this warp's m-tile, 16 rows x 64 keys)
    const uint32_t pA = sb + SM_P + (mt * 16 + (lane & 15)) * PROW + ((lane >> 4) & 1) * 16;

    // prologue: Q (group 0), K0/V0 (group 1)
    {
        const __nv_bfloat16* qp = Qg + ((size_t)b * HW + q0) * DQK;
        #pragma unroll
        for (int t = tid; t < 32 * 8; t += 128) {
            int r = t >> 3, c8 = t & 7;
            cp_async16(sb + SM_Q + r * KROW + c8 * 16, qp + r * DQK + c8 * 8);
        }
        CP_COMMIT();
        issue_kv(sb, SM_K0, SM_V0, b, 0, tid);
        CP_COMMIT();
    }

    // Q A-frags for this warp's m-tile
    uint32_t aq[4][4];
    {
        asm volatile("cp.async.wait_group 1;" ::: "memory");
        __syncthreads();
        const uint32_t qbase = sb + SM_Q + (mt * 16 + qr) * KROW + m4 * 4;
        #pragma unroll
        for (int ks = 0; ks < 4; ks++) {
            aq[ks][0] = lds_b32(qbase + ks * 32);
            aq[ks][1] = lds_b32(qbase + 8 * KROW + ks * 32);
            aq[ks][2] = lds_b32(qbase + ks * 32 + 16);
            aq[ks][3] = lds_b32(qbase + 8 * KROW + ks * 32 + 16);
        }
    }

    float oacc[16][4];
    #pragma unroll
    for (int nt = 0; nt < 16; nt++)
        #pragma unroll
        for (int c = 0; c < 4; c++) oacc[nt][c] = 0.f;
    float dden[4];
    #pragma unroll
    for (int c = 0; c < 4; c++) dden[c] = 0.f;

    // P store base for this warp: rows of its m-tile, its 32-key half
    const uint32_t pstore = sb + SM_P + (mt * 16 + qr) * PROW + half * 64 + m4 * 4;
    const int pair_bar = 1 + mt;

    #pragma unroll 1
    for (int j = 0; j < NITER; j++) {
        const int koff = (j & 1) ? SM_K1 : SM_K0;
        const int voff = (j & 1) ? SM_V1 : SM_V0;

        asm volatile("cp.async.wait_group 0;" ::: "memory");
        __syncthreads();   // K/V(j) visible; all PV(j-1) reads done

        // prefetch K/V(j+1) IMMEDIATELY (full-iteration distance)
        if (j + 1 < NITER)
            issue_kv(sb, (j & 1) ? SM_K0 : SM_K1, (j & 1) ? SM_V0 : SM_V1,
                     b, (j + 1) * BK, tid);
        CP_COMMIT();

        // ---- S phase: 16q x 32k for (mt, key-half) -> P, den ----
        {
            uint32_t paLo[4], paHi[4];
            #pragma unroll
            for (int tp2 = 0; tp2 < 2; tp2++) {
                const uint32_t kbase = sb + koff + (half * 32 + tp2 * 16) * KROW + lmoffK;
                float s2[2][4];
                #pragma unroll
                for (int nh = 0; nh < 2; nh++)
                    #pragma unroll
                    for (int c = 0; c < 4; c++) s2[nh][c] = 0.f;
                #pragma unroll
                for (int ks = 0; ks < 4; ks++) {
                    uint32_t kf[4];
                    ldmx4(kf, kbase + ks * 32);
                    mma16816(s2[0], aq[ks][0], aq[ks][1], aq[ks][2], aq[ks][3], kf[0], kf[1]);
                    mma16816(s2[1], aq[ks][0], aq[ks][1], aq[ks][2], aq[ks][3], kf[2], kf[3]);
                }
                #pragma unroll
                for (int nh = 0; nh < 2; nh++) {
                    const int nt = tp2 * 2 + nh;
                    paLo[nt] = ex2_b2(cvt_bf16x2(s2[nh][0], s2[nh][1]));
                    paHi[nt] = ex2_b2(cvt_bf16x2(s2[nh][2], s2[nh][3]));
                    sts_b32(pstore + nt * 16,            paLo[nt]);
                    sts_b32(pstore + 8 * PROW + nt * 16, paHi[nt]);
                }
            }
            // den += P . ones (two k16 chunks of this 32-key half)
            mma16816(dden, paLo[0], paHi[0], paLo[1], paHi[1], ONESB2, ONESB2);
            mma16816(dden, paLo[2], paHi[2], paLo[3], paHi[3], ONESB2, ONESB2);
        }

        // P pair-visible (only the 2 warps sharing this m-tile need it)
        asm volatile("bar.sync %0, 64;" :: "r"(pair_bar) : "memory");

        // ---- PV phase: 16q x 128ch x 64k for (mt, chan-half) ----
        {
            uint32_t pf[4][4];
            #pragma unroll
            for (int ks2 = 0; ks2 < 4; ks2++)
                ldmx4(pf[ks2], pA + ks2 * 32);
            const uint32_t vbase = sb + voff + half * 128 * VROW + lmoffV;
            #pragma unroll
            for (int ks2 = 0; ks2 < 4; ks2++) {
                #pragma unroll
                for (int ntp = 0; ntp < 8; ntp++) {
                    uint32_t vf[4];
                    ldmx4(vf, vbase + ntp * (16 * VROW) + ks2 * 32);
                    mma16816(oacc[2 * ntp],     pf[ks2][0], pf[ks2][1],
                             pf[ks2][2], pf[ks2][3], vf[0], vf[1]);
                    mma16816(oacc[2 * ntp + 1], pf[ks2][0], pf[ks2][1],
                             pf[ks2][2], pf[ks2][3], vf[2], vf[3]);
                }
            }
        }
    }

    // ---- den: combine key-halves across the pair ----
    float* den_sm = (float*)(smem + SM_DEN);   // [2 halves][32 rows]
    const int row = mt * 16 + qr;
    den_sm[half * 32 + row]     = dden[0];
    den_sm[half * 32 + row + 8] = dden[2];
    __syncthreads();
    const float gamma = __ldg(gammap);
    const float scl0 = gamma / (den_sm[row]     + den_sm[32 + row]);
    const float scl8 = gamma / (den_sm[row + 8] + den_sm[32 + row + 8]);
    __syncthreads();

    // ---- epilogue: stage [256 ch][36] fp32 at smem offset 0, coalesced out ----
    float* stg = (float*)smem;
    #pragma unroll
    for (int nt = 0; nt < 16; nt++) {
        const int ch = half * 128 + nt * 8 + 2 * m4;
        stg[ch * STGROW + row]           = oacc[nt][0] * scl0;
        stg[(ch + 1) * STGROW + row]     = oacc[nt][1] * scl0;
        stg[ch * STGROW + row + 8]       = oacc[nt][2] * scl8;
        stg[(ch + 1) * STGROW + row + 8] = oacc[nt][3] * scl8;
    }
    __syncthreads();
    const float* sp = srcf + (size_t)b * CIN * HW;
    float*       op = out  + (size_t)b * CIN * HW;
    #pragma unroll
    for (int idx = tid; idx < 256 * 8; idx += 128) {
        const int ch = idx >> 3, qq = (idx & 7) * 4;
        float4 v = *(const float4*)&stg[ch * STGROW + qq];
        const size_t g = (size_t)ch * HW + q0 + qq;
        float4 s4 = *(const float4*)&sp[g];
        v.x += s4.x; v.y += s4.y; v.z += s4.z; v.w += s4.w;
        *(float4*)&op[g] = v;
    }
}

// ============================================================
extern "C" void kernel_launch(void* const* d_in, const int* in_sizes, int n_in,
                              void* d_out, int out_size)
{
    const float* src    = (const float*)d_in[0];
    const float* ref    = (const float*)d_in[1];
    const float* w_src  = (const float*)d_in[2];
    const float* b_src  = (const float*)d_in[3];
    const float* w_ref  = (const float*)d_in[4];
    const float* b_ref  = (const float*)d_in[5];
    const float* w_gate = (const float*)d_in[6];
    const float* b_gate = (const float*)d_in[7];
    const float* gamma  = (const float*)d_in[8];
    float* out = (float*)d_out;

    cudaFuncSetAttribute(proj_tc, cudaFuncAttributeMaxDynamicSharedMemorySize, P_TOTAL);
    cudaFuncSetAttribute(attn_kernel, cudaFuncAttributeMaxDynamicSharedMemorySize, SM_TOTAL);

    proj_tc<<<dim3(HW / 128, NB, 6), 128, P_TOTAL>>>(src, ref, w_src, b_src,
                                                     w_ref, b_ref, w_gate, b_gate);
    attn_kernel<<<dim3(HW / BQ, NB), 128, SM_TOTAL>>>(src, gamma, out);
}

// round 16
// speedup vs baseline: 1.3966x; 1.0345x over previous
#include <cuda_runtime.h>
#include <cuda_bf16.h>
#include <cstdint>

#define HW   4096
#define NB   4
#define CIN  256
#define DQK  64
#define BQ   128          // queries per CTA (4 warps x 32 rows)
#define BK   64           // keys per iteration
#define NITER (HW / BK)   // 64
#define CHPC 64           // channels per CTA (z-split x4)

// (1/16) * log2(e), folded into Q at projection time
#define QSCL (0.0625f * 1.44269504088896f)
#define ONESB2 0x3F803F80u   /* bf16x2 {1.0, 1.0} */

// ---------------- scratch (bf16) ----------------
__device__ __nv_bfloat16 Qg[NB * HW * DQK];        // [b][i][k]   2 MB (pre-scaled)
__device__ __nv_bfloat16 Kg[NB * HW * DQK];        // [b][j][k]   2 MB
__device__ __nv_bfloat16 Vtg[NB * CIN * HW];       // [b][c][j]   8 MB (channel-major)

// ---------------- helpers ----------------
__device__ __forceinline__ uint32_t smem_u32(const void* p) {
    uint32_t a;
    asm("{ .reg .u64 t; cvta.to.shared.u64 t, %1; cvt.u32.u64 %0, t; }" : "=r"(a) : "l"(p));
    return a;
}
__device__ __forceinline__ void cp_async16(uint32_t dst, const void* src) {
    asm volatile("cp.async.cg.shared.global [%0], [%1], 16;" :: "r"(dst), "l"(src));
}
#define CP_COMMIT() asm volatile("cp.async.commit_group;" ::: "memory")

__device__ __forceinline__ uint32_t lds_b32(uint32_t a) {
    uint32_t v;
    asm volatile("ld.shared.b32 %0, [%1];" : "=r"(v) : "r"(a));
    return v;
}
__device__ __forceinline__ void ldmx4(uint32_t* r, uint32_t a) {
    asm volatile("ldmatrix.sync.aligned.m8n8.x4.shared.b16 {%0,%1,%2,%3}, [%4];"
                 : "=r"(r[0]), "=r"(r[1]), "=r"(r[2]), "=r"(r[3]) : "r"(a));
}
__device__ __forceinline__ uint32_t cvt_bf16x2(float lo, float hi) {
    uint32_t r;
    asm("cvt.rn.bf16x2.f32 %0, %1, %2;" : "=r"(r) : "f"(hi), "f"(lo));
    return r;
}
__device__ __forceinline__ uint32_t ex2_b2(uint32_t x) {
    uint32_t r;
    asm("ex2.approx.ftz.bf16x2 %0, %1;" : "=r"(r) : "r"(x));
    return r;
}
// D += A(16x16,row) * B(16x8,col)  bf16 -> f32
__device__ __forceinline__ void mma16816(float* c,
                                         uint32_t a0, uint32_t a1, uint32_t a2, uint32_t a3,
                                         uint32_t b0, uint32_t b1) {
    asm volatile(
        "mma.sync.aligned.m16n8k16.row.col.f32.bf16.bf16.f32 "
        "{%0,%1,%2,%3}, {%4,%5,%6,%7}, {%8,%9}, {%0,%1,%2,%3};"
        : "+f"(c[0]), "+f"(c[1]), "+f"(c[2]), "+f"(c[3])
        : "r"(a0), "r"(a1), "r"(a2), "r"(a3), "r"(b0), "r"(b1));
}
// D += A(16x8,row) * B(8x8,col)  tf32 -> f32
__device__ __forceinline__ void mma_tf32(float* c,
                                         uint32_t a0, uint32_t a1, uint32_t a2, uint32_t a3,
                                         uint32_t b0, uint32_t b1) {
    asm volatile(
        "mma.sync.aligned.m16n8k8.row.col.f32.tf32.tf32.f32 "
        "{%0,%1,%2,%3}, {%4,%5,%6,%7}, {%8,%9}, {%0,%1,%2,%3};"
        : "+f"(c[0]), "+f"(c[1]), "+f"(c[2]), "+f"(c[3])
        : "r"(a0), "r"(a1), "r"(a2), "r"(a3), "r"(b0), "r"(b1));
}

// ---------------- attn SMEM layout (bytes) ----------------
// 4-slot KV ring; slot = 18432 B (K 9216 + V 9216). Slot 2 overlays the Q
// region (Q is dead after the prologue fragment loads).
// rows padded to 144 B (9 x 16B: ldmatrix conflict-free)
#define KROW    144
#define VROW    144
#define KVHALF  9216               // 64 rows x 144
#define SM_Q    0                  // 128 x 144 = 18432 (== ring slot 2)
#define SM_TOTAL 73728
// slot bases: KV(j) lives in slot j%4
// slot0 @ 18432, slot1 @ 36864, slot2 @ 0 (Q region), slot3 @ 55296

// ---------------- proj SMEM layout (bytes) ----------------
#define XROWB 544
#define WROWB 272
#define PX0 0
#define PX1 34816
#define PW0 69632
#define PW1 87040
#define P_TOTAL 104448
#define PSTGROW 144

// ============================================================
// Projection via tf32 tensor cores. (unchanged from round 10)
// ============================================================
__global__ __launch_bounds__(128, 2) void proj_tc(
    const float* __restrict__ src, const float* __restrict__ ref,
    const float* __restrict__ w_src, const float* __restrict__ b_src,
    const float* __restrict__ w_ref, const float* __restrict__ b_ref,
    const float* __restrict__ w_gate, const float* __restrict__ b_gate)
{
    extern __shared__ char smem[];
    const uint32_t sb = smem_u32(smem);
    const int tid  = threadIdx.x;
    const int warp = tid >> 5;
    const int lane = tid & 31;
    const int row4 = lane >> 2;
    const int q4   = lane & 3;
    const int z    = blockIdx.z;
    const int b    = blockIdx.y;
    const int i0   = blockIdx.x * 128;

    const float *X, *W, *bias;
    if (z == 0)      { X = src; W = w_src;                       bias = b_src; }
    else if (z == 1) { X = ref; W = w_ref;                       bias = b_ref; }
    else             { X = ref; W = w_gate + (z - 2) * 64 * CIN; bias = b_gate + (z - 2) * 64; }
    const float* Xb = X + (size_t)b * CIN * HW;

    auto issue_chunk = [&](int kc, int buf) {
        const uint32_t xb = sb + (buf ? PX1 : PX0);
        const uint32_t wb = sb + (buf ? PW1 : PW0);
        #pragma unroll
        for (int t = tid; t < 64 * 32; t += 128) {
            int r = t >> 5, s = t & 31;
            cp_async16(xb + r * XROWB + s * 16, Xb + (size_t)(kc * 64 + r) * HW + i0 + s * 4);
        }
        #pragma unroll
        for (int t = tid; t < 64 * 16; t += 128) {
            int r = t >> 4, s = t & 15;
            cp_async16(wb + r * WROWB + s * 16, W + r * CIN + kc * 64 + s * 4);
        }
    };

    issue_chunk(0, 0);
    CP_COMMIT();

    float acc[16][4];
    #pragma unroll
    for (int nt = 0; nt < 16; nt++)
        #pragma unroll
        for (int c = 0; c < 4; c++) acc[nt][c] = 0.f;

    #pragma unroll 1
    for (int kc = 0; kc < 4; kc++) {
        if (kc + 1 < 4) {
            issue_chunk(kc + 1, (kc + 1) & 1);
            CP_COMMIT();
            asm volatile("cp.async.wait_group 1;" ::: "memory");
        } else {
            asm volatile("cp.async.wait_group 0;" ::: "memory");
        }
        __syncthreads();

        const uint32_t xb = sb + ((kc & 1) ? PX1 : PX0);
        const uint32_t wb = sb + ((kc & 1) ? PW1 : PW0);
        const uint32_t abase = wb + (warp * 16 + row4) * WROWB + q4 * 4;
        const uint32_t bbase = xb + q4 * XROWB + row4 * 4;

        #pragma unroll
        for (int ks = 0; ks < 8; ks++) {
            uint32_t a0 = lds_b32(abase + ks * 32);
            uint32_t a1 = lds_b32(abase + 8 * WROWB + ks * 32);
            uint32_t a2 = lds_b32(abase + ks * 32 + 16);
            uint32_t a3 = lds_b32(abase + 8 * WROWB + ks * 32 + 16);
            const uint32_t bk = bbase + ks * 8 * XROWB;
            #pragma unroll
            for (int nt = 0; nt < 16; nt++) {
                uint32_t b0 = lds_b32(bk + nt * 32);
                uint32_t b1 = lds_b32(bk + 4 * XROWB + nt * 32);
                mma_tf32(acc[nt], a0, a1, a2, a3, b0, b1);
            }
        }
        __syncthreads();
    }

    const int olo = warp * 16 + row4;
    const float bv0 = bias[olo];
    const float bv8 = bias[olo + 8];

    if (z >= 2) {
        const int ch0 = (z - 2) * 64;
        #pragma unroll
        for (int nt = 0; nt < 16; nt++) {
            const int i = i0 + nt * 8 + 2 * q4;
            *(uint32_t*)(Vtg + ((size_t)(b * CIN + ch0 + olo)) * HW + i) =
                cvt_bf16x2(acc[nt][0] + bv0, acc[nt][1] + bv0);
            *(uint32_t*)(Vtg + ((size_t)(b * CIN + ch0 + olo + 8)) * HW + i) =
                cvt_bf16x2(acc[nt][2] + bv8, acc[nt][3] + bv8);
        }
    } else {
        const float s = (z == 0) ? QSCL : 1.0f;
        __nv_bfloat16* stg = (__nv_bfloat16*)smem;
        #pragma unroll
        for (int nt = 0; nt < 16; nt++) {
            const int i = nt * 8 + 2 * q4;
            __nv_bfloat16* r0 = stg + (size_t)i * (PSTGROW / 2);
            r0[olo]     = __float2bfloat16((acc[nt][0] + bv0) * s);
            r0[olo + 8] = __float2bfloat16((acc[nt][2] + bv8) * s);
            __nv_bfloat16* r1 = stg + (size_t)(i + 1) * (PSTGROW / 2);
            r1[olo]     = __float2bfloat16((acc[nt][1] + bv0) * s);
            r1[olo + 8] = __float2bfloat16((acc[nt][3] + bv8) * s);
        }
        __syncthreads();
        __nv_bfloat16* outp = (z == 0 ? Qg : Kg) + ((size_t)b * HW + i0) * DQK;
        #pragma unroll
        for (int t = tid; t < 1024; t += 128) {
            int r = t >> 3, seg = t & 7;
            *(uint4*)(outp + (size_t)r * DQK + seg * 8) =
                *(uint4*)((char*)smem + r * PSTGROW + seg * 16);
        }
    }
}

// ============================================================
// bf16 HMMA flash attention, 4-slot KV ring, ONE barrier/iter.
// Order per iter: prefetch(j+2) -> commit -> wait own -> barrier -> compute(j).
// grid (HW/BQ=32, NB, 4): z selects 64 output channels.
// ============================================================
__device__ __forceinline__ void issue_kv(uint32_t sb, uint32_t base,
                                         int b, int z, int j0, int tid)
{
    const __nv_bfloat16* kp = Kg + ((size_t)b * HW + j0) * DQK;
    #pragma unroll
    for (int t = tid; t < 64 * 8; t += 128) {
        int r = t >> 3, c8 = t & 7;
        cp_async16(sb + base + r * KROW + c8 * 16, kp + r * DQK + c8 * 8);
    }
    #pragma unroll
    for (int t = tid; t < 64 * 8; t += 128) {
        int c = t >> 3, c8 = t & 7;
        cp_async16(sb + base + KVHALF + c * VROW + c8 * 16,
                   Vtg + ((size_t)(b * CIN + z * CHPC + c)) * HW + j0 + c8 * 8);
    }
}

__global__ __launch_bounds__(128, 3) void attn_kernel(
    const float* __restrict__ srcf, const float* __restrict__ gammap,
    float* __restrict__ out)
{
    extern __shared__ char smem[];
    const uint32_t sb = smem_u32(smem);
    const int tid  = threadIdx.x;
    const int warp = tid >> 5;
    const int lane = tid & 31;
    const int b    = blockIdx.y;
    const int z    = blockIdx.z;
    const int q0   = blockIdx.x * BQ;
    const int qr   = (lane >> 2);
    const int m4   = (lane & 3);

    const uint32_t lmoff = (uint32_t)((((lane >> 4) & 1) * 8 + (lane & 7)) * KROW
                                      + ((lane >> 3) & 1) * 16);

    // prologue: Q (group 0), KV(0)->slot0 (group 1), KV(1)->slot1 (group 2)
    {
        const __nv_bfloat16* qp = Qg + ((size_t)b * HW + q0) * DQK;
        #pragma unroll
        for (int t = tid; t < 128 * 8; t += 128) {
            int r = t >> 3, c8 = t & 7;
            cp_async16(sb + SM_Q + r * KROW + c8 * 16, qp + r * DQK + c8 * 8);
        }
        CP_COMMIT();
        issue_kv(sb, 18432u, b, z, 0, tid);
        CP_COMMIT();
        issue_kv(sb, 36864u, b, z, BK, tid);
        CP_COMMIT();
    }

    // wait for Q (own), barrier (everyone's Q visible), load Q A-frags
    uint32_t aq[2][4][4];
    {
        asm volatile("cp.async.wait_group 2;" ::: "memory");
        __syncthreads();
        #pragma unroll
        for (int mt = 0; mt < 2; mt++) {
            const uint32_t qbase = sb + SM_Q + (warp * 32 + mt * 16 + qr) * KROW + m4 * 4;
            #pragma unroll
            for (int ks = 0; ks < 4; ks++) {
                aq[mt][ks][0] = lds_b32(qbase + ks * 32);
                aq[mt][ks][1] = lds_b32(qbase + 8 * KROW + ks * 32);
                aq[mt][ks][2] = lds_b32(qbase + ks * 32 + 16);
                aq[mt][ks][3] = lds_b32(qbase + 8 * KROW + ks * 32 + 16);
            }
        }
        __syncthreads();   // all aq reads done before slot2 (=Q region) is overwritten
    }

    float oacc[2][8][4];
    #pragma unroll
    for (int mt = 0; mt < 2; mt++)
        #pragma unroll
        for (int nt = 0; nt < 8; nt++)
            #pragma unroll
            for (int c = 0; c < 4; c++) oacc[mt][nt][c] = 0.f;
    float dden[2][4];
    #pragma unroll
    for (int mt = 0; mt < 2; mt++)
        #pragma unroll
        for (int c = 0; c < 4; c++) dden[mt][c] = 0.f;

    #pragma unroll 1
    for (int j4 = 0; j4 < NITER; j4 += 4) {
        #pragma unroll
        for (int u = 0; u < 4; u++) {
            const int j = j4 + u;
            // slot bases: KV(s) in slot s%4: {0->18432, 1->36864, 2->0, 3->55296}
            constexpr uint32_t SBASE[4] = {18432u, 36864u, 0u, 55296u};
            const uint32_t rbase = SBASE[u];
            const uint32_t wbase = SBASE[(u + 2) & 3];

            // prefetch KV(j+2), then wait for OWN KV(j), then barrier
            if (j + 2 < NITER)
                issue_kv(sb, wbase, b, z, (j + 2) * BK, tid);
            CP_COMMIT();
            asm volatile("cp.async.wait_group 2;" ::: "memory");
            __syncthreads();   // everyone's KV(j) visible; PV(j-1) reads ordered

            const uint32_t kbase = sb + rbase + lmoff;
            const uint32_t vbase = sb + rbase + KVHALF + lmoff;

            // ---- fused: per 16-key slab: S -> exp -> PV ----
            #pragma unroll
            for (int tp = 0; tp < 4; tp++) {
                uint32_t kf[4][4];
                #pragma unroll
                for (int ks = 0; ks < 4; ks++)
                    ldmx4(kf[ks], kbase + tp * (16 * KROW) + ks * 32);

                float s[2][2][4];
                #pragma unroll
                for (int mt = 0; mt < 2; mt++)
                    #pragma unroll
                    for (int nh = 0; nh < 2; nh++)
                        #pragma unroll
                        for (int c = 0; c < 4; c++) s[mt][nh][c] = 0.f;
                #pragma unroll
                for (int ks = 0; ks < 4; ks++)
                    #pragma unroll
                    for (int mt = 0; mt < 2; mt++) {
                        mma16816(s[mt][0], aq[mt][ks][0], aq[mt][ks][1],
                                 aq[mt][ks][2], aq[mt][ks][3], kf[ks][0], kf[ks][1]);
                        mma16816(s[mt][1], aq[mt][ks][0], aq[mt][ks][1],
                                 aq[mt][ks][2], aq[mt][ks][3], kf[ks][2], kf[ks][3]);
                    }

                uint32_t pa[2][4];
                #pragma unroll
                for (int mt = 0; mt < 2; mt++) {
                    pa[mt][0] = ex2_b2(cvt_bf16x2(s[mt][0][0], s[mt][0][1]));
                    pa[mt][1] = ex2_b2(cvt_bf16x2(s[mt][0][2], s[mt][0][3]));
                    pa[mt][2] = ex2_b2(cvt_bf16x2(s[mt][1][0], s[mt][1][1]));
                    pa[mt][3] = ex2_b2(cvt_bf16x2(s[mt][1][2], s[mt][1][3]));
                    mma16816(dden[mt], pa[mt][0], pa[mt][1], pa[mt][2], pa[mt][3],
                             ONESB2, ONESB2);
                }

                #pragma unroll
                for (int ntp = 0; ntp < 4; ntp++) {
                    uint32_t vf[4];
                    ldmx4(vf, vbase + tp * 32 + ntp * (16 * VROW));
                    #pragma unroll
                    for (int mt = 0; mt < 2; mt++) {
                        mma16816(oacc[mt][2 * ntp],     pa[mt][0], pa[mt][1],
                                 pa[mt][2], pa[mt][3], vf[0], vf[1]);
                        mma16816(oacc[mt][2 * ntp + 1], pa[mt][0], pa[mt][1],
                                 pa[mt][2], pa[mt][3], vf[2], vf[3]);
                    }
                }
            }
            // no end barrier: slot reuse is protected by the barrier at iter j+1/j+2
        }
    }

    const float gamma = __ldg(gammap);
    float scl[2][2];
    #pragma unroll
    for (int mt = 0; mt < 2; mt++) {
        scl[mt][0] = gamma / dden[mt][0];
        scl[mt][1] = gamma / dden[mt][2];
    }

    __syncthreads();   // all PV done before staging overwrites the ring
    float* stg = (float*)smem;   // [64 ch][132] floats = 33792 B
    const float* sp = srcf + (size_t)b * CIN * HW;
    float*       op = out  + (size_t)b * CIN * HW;

    #pragma unroll
    for (int mt = 0; mt < 2; mt++) {
        const int q = warp * 32 + mt * 16 + qr;
        #pragma unroll
        for (int nt = 0; nt < 8; nt++) {
            const int ch = nt * 8 + 2 * m4;
            stg[ch * 132 + q]             = oacc[mt][nt][0] * scl[mt][0];
            stg[(ch + 1) * 132 + q]       = oacc[mt][nt][1] * scl[mt][0];
            stg[ch * 132 + q + 8]         = oacc[mt][nt][2] * scl[mt][1];
            stg[(ch + 1) * 132 + q + 8]   = oacc[mt][nt][3] * scl[mt][1];
        }
    }
    __syncthreads();
    #pragma unroll
    for (int idx = tid; idx < 64 * 32; idx += 128) {
        const int ch = idx >> 5, q4 = idx & 31;
        float4 v = *(const float4*)&stg[ch * 132 + q4 * 4];
        const size_t g = (size_t)(z * CHPC + ch) * HW + q0 + q4 * 4;
        float4 s4 = *(const float4*)&sp[g];
        v.x += s4.x; v.y += s4.y; v.z += s4.z; v.w += s4.w;
        *(float4*)&op[g] = v;
    }
}

// ============================================================
extern "C" void kernel_launch(void* const* d_in, const int* in_sizes, int n_in,
                              void* d_out, int out_size)
{
    const float* src    = (const float*)d_in[0];
    const float* ref    = (const float*)d_in[1];
    const float* w_src  = (const float*)d_in[2];
    const float* b_src  = (const float*)d_in[3];
    const float* w_ref  = (const float*)d_in[4];
    const float* b_ref  = (const float*)d_in[5];
    const float* w_gate = (const float*)d_in[6];
    const float* b_gate = (const float*)d_in[7];
    const float* gamma  = (const float*)d_in[8];
    float* out = (float*)d_out;

    cudaFuncSetAttribute(proj_tc, cudaFuncAttributeMaxDynamicSharedMemorySize, P_TOTAL);
    cudaFuncSetAttribute(attn_kernel, cudaFuncAttributeMaxDynamicSharedMemorySize, SM_TOTAL);

    proj_tc<<<dim3(HW / 128, NB, 6), 128, P_TOTAL>>>(src, ref, w_src, b_src,
                                                     w_ref, b_ref, w_gate, b_gate);
    attn_kernel<<<dim3(HW / BQ, NB, 4), 128, SM_TOTAL>>>(src, gamma, out);
}